// round 10
// baseline (speedup 1.0000x reference)
#include <cuda_runtime.h>
#include <math.h>

#define BB 2
#define SS 2048
#define DD 1024
#define HH 16
#define DK 64
#define M_TOT (BB*SS)
#define PH 72            // smem pitch in halves (144B rows, conflict-free)

typedef unsigned short ushort_t;

// Scratch (__device__ globals only; 16B-aligned for vector ld/st)
__device__ __align__(16) ushort_t g_qh[(size_t)BB*HH*SS*DK];
__device__ __align__(16) ushort_t g_ql[(size_t)BB*HH*SS*DK];
__device__ __align__(16) ushort_t g_kh[(size_t)BB*HH*SS*DK];
__device__ __align__(16) ushort_t g_kl[(size_t)BB*HH*SS*DK];
__device__ __align__(16) ushort_t g_vh[(size_t)BB*HH*SS*DK];
__device__ __align__(16) ushort_t g_vl[(size_t)BB*HH*SS*DK];
__device__ __align__(16) float    g_attn[(size_t)BB*SS*DD];

// ---------------------------------------------------------------------------
// helpers
// ---------------------------------------------------------------------------
__device__ __forceinline__ unsigned f2tf32(float x) {
    unsigned r; asm("cvt.rna.tf32.f32 %0, %1;" : "=r"(r) : "f"(x)); return r;
}
__device__ __forceinline__ void mma_tf32(float c[4], const unsigned a[4], const unsigned b[2]) {
    asm volatile(
        "mma.sync.aligned.m16n8k8.row.col.f32.tf32.tf32.f32 "
        "{%0,%1,%2,%3}, {%4,%5,%6,%7}, {%8,%9}, {%0,%1,%2,%3};\n"
        : "+f"(c[0]), "+f"(c[1]), "+f"(c[2]), "+f"(c[3])
        : "r"(a[0]), "r"(a[1]), "r"(a[2]), "r"(a[3]), "r"(b[0]), "r"(b[1]));
}
__device__ __forceinline__ void mma_bf16(float c[4], const unsigned a[4],
                                         unsigned b0, unsigned b1) {
    asm volatile(
        "mma.sync.aligned.m16n8k16.row.col.f32.bf16.bf16.f32 "
        "{%0,%1,%2,%3}, {%4,%5,%6,%7}, {%8,%9}, {%0,%1,%2,%3};\n"
        : "+f"(c[0]), "+f"(c[1]), "+f"(c[2]), "+f"(c[3])
        : "r"(a[0]), "r"(a[1]), "r"(a[2]), "r"(a[3]), "r"(b0), "r"(b1));
}
__device__ __forceinline__ unsigned su32(const void* p) {
    return (unsigned)__cvta_generic_to_shared(p);
}
__device__ __forceinline__ void ldsm4(unsigned r[4], unsigned a) {
    asm volatile("ldmatrix.sync.aligned.m8n8.x4.shared.b16 {%0,%1,%2,%3}, [%4];"
        : "=r"(r[0]), "=r"(r[1]), "=r"(r[2]), "=r"(r[3]) : "r"(a));
}
__device__ __forceinline__ void ldsm4t(unsigned r[4], unsigned a) {
    asm volatile("ldmatrix.sync.aligned.m8n8.x4.trans.shared.b16 {%0,%1,%2,%3}, [%4];"
        : "=r"(r[0]), "=r"(r[1]), "=r"(r[2]), "=r"(r[3]) : "r"(a));
}
__device__ __forceinline__ float ex2(float x) {
    float y; asm("ex2.approx.f32 %0, %1;" : "=f"(y) : "f"(x)); return y;
}
__device__ __forceinline__ void pack_split(unsigned &hi, unsigned &lo, float v0, float v1) {
    asm("cvt.rn.bf16x2.f32 %0, %1, %2;" : "=r"(hi) : "f"(v1), "f"(v0));
    const float h0 = __uint_as_float(hi << 16);
    const float h1 = __uint_as_float(hi & 0xffff0000u);
    asm("cvt.rn.bf16x2.f32 %0, %1, %2;" : "=r"(lo) : "f"(v1 - h1), "f"(v0 - h0));
}
__device__ __forceinline__ void cpa16(unsigned saddr, const void* g) {
    asm volatile("cp.async.cg.shared.global [%0], [%1], 16;" :: "r"(saddr), "l"(g));
}
__device__ __forceinline__ void cpa_commit() { asm volatile("cp.async.commit_group;"); }
template<int N> __device__ __forceinline__ void cpa_wait() {
    asm volatile("cp.async.wait_group %0;" :: "n"(N));
}

// ---------------------------------------------------------------------------
// tf32 projection GEMM, register-staged software pipeline. (round-6 verified)
// MODE 0: fp32 store out[m*D+n]                               (wo)
// MODE 1: bf16 hi/lo split store [b,h,s,d]                    (V)
// MODE 2: RoPE + scale, bf16 hi/lo split store [b,h,s,d]      (Q/K)
// CTA tile 128x64xK32, 256 thr, warp tile 32x32.
// ---------------------------------------------------------------------------
template<int MODE>
__global__ __launch_bounds__(256)
void proj_tc(const float* __restrict__ x, const float* __restrict__ w,
             const int* __restrict__ tp, float* __restrict__ outf,
             ushort_t* __restrict__ oh, ushort_t* __restrict__ ol, float scale)
{
    __shared__ unsigned As[128][36];
    __shared__ unsigned Ws[64][36];

    const int tid  = threadIdx.x;
    const int lane = tid & 31;
    const int wid  = tid >> 5;
    const int g    = lane >> 2;
    const int t    = lane & 3;
    const int wm   = wid >> 1;
    const int wn   = wid & 1;
    const int m0   = blockIdx.y * 128;
    const int n0   = blockIdx.x * 64;

    const int lrow = tid >> 3;
    const int lcs  = (tid & 7) * 4;
    const float* xb = x + (size_t)(m0 + lrow) * DD + lcs;
    const float* wb = w + (size_t)(n0 + lrow) * DD + lcs;

    float acc[2][4][4] = {};
    float4 abuf[4], wbuf[2];

#pragma unroll
    for (int p = 0; p < 4; p++) abuf[p] = *(const float4*)(xb + (size_t)p * 32 * DD);
#pragma unroll
    for (int p = 0; p < 2; p++) wbuf[p] = *(const float4*)(wb + (size_t)p * 32 * DD);
#pragma unroll
    for (int p = 0; p < 4; p++)
        *(uint4*)&As[lrow + p * 32][lcs] = make_uint4(f2tf32(abuf[p].x), f2tf32(abuf[p].y),
                                                      f2tf32(abuf[p].z), f2tf32(abuf[p].w));
#pragma unroll
    for (int p = 0; p < 2; p++)
        *(uint4*)&Ws[lrow + p * 32][lcs] = make_uint4(f2tf32(wbuf[p].x), f2tf32(wbuf[p].y),
                                                      f2tf32(wbuf[p].z), f2tf32(wbuf[p].w));
    __syncthreads();

    for (int k0 = 0; k0 < DD; k0 += 32) {
        const bool more = (k0 + 32 < DD);
        if (more) {
#pragma unroll
            for (int p = 0; p < 4; p++) abuf[p] = *(const float4*)(xb + (size_t)p * 32 * DD + k0 + 32);
#pragma unroll
            for (int p = 0; p < 2; p++) wbuf[p] = *(const float4*)(wb + (size_t)p * 32 * DD + k0 + 32);
        }

#pragma unroll
        for (int kk = 0; kk < 32; kk += 8) {
            unsigned af[2][4], bf[4][2];
#pragma unroll
            for (int i = 0; i < 2; i++) {
                const int rb = wm * 32 + i * 16;
                af[i][0] = As[rb + g    ][kk + t    ];
                af[i][1] = As[rb + g + 8][kk + t    ];
                af[i][2] = As[rb + g    ][kk + t + 4];
                af[i][3] = As[rb + g + 8][kk + t + 4];
            }
#pragma unroll
            for (int j = 0; j < 4; j++) {
                const int nb = wn * 32 + j * 8;
                bf[j][0] = Ws[nb + g][kk + t    ];
                bf[j][1] = Ws[nb + g][kk + t + 4];
            }
#pragma unroll
            for (int i = 0; i < 2; i++)
#pragma unroll
                for (int j = 0; j < 4; j++)
                    mma_tf32(acc[i][j], af[i], bf[j]);
        }
        __syncthreads();
        if (more) {
#pragma unroll
            for (int p = 0; p < 4; p++)
                *(uint4*)&As[lrow + p * 32][lcs] = make_uint4(f2tf32(abuf[p].x), f2tf32(abuf[p].y),
                                                              f2tf32(abuf[p].z), f2tf32(abuf[p].w));
#pragma unroll
            for (int p = 0; p < 2; p++)
                *(uint4*)&Ws[lrow + p * 32][lcs] = make_uint4(f2tf32(wbuf[p].x), f2tf32(wbuf[p].y),
                                                              f2tf32(wbuf[p].z), f2tf32(wbuf[p].w));
            __syncthreads();
        }
    }

#pragma unroll
    for (int i = 0; i < 2; i++) {
        const int row0 = m0 + wm * 32 + i * 16 + g;
        const int row1 = row0 + 8;
#pragma unroll
        for (int j = 0; j < 4; j++) {
            const int col = n0 + wn * 32 + j * 8 + 2 * t;   // even
            float v00 = acc[i][j][0], v01 = acc[i][j][1];
            float v10 = acc[i][j][2], v11 = acc[i][j][3];
            if (MODE == 0) {
                *(float2*)(outf + (size_t)row0 * DD + col) = make_float2(v00, v01);
                *(float2*)(outf + (size_t)row1 * DD + col) = make_float2(v10, v11);
            } else {
                const int h = col >> 6, d = col & 63;       // d even
                if (MODE == 2) {
                    const float fr = (float)exp2(-(double)d * 0.20762050593046014);
                    float s0, c0, s1, c1;
                    sincosf((float)tp[row0] * fr, &s0, &c0);
                    sincosf((float)tp[row1] * fr, &s1, &c1);
                    const float e0 = v00, o0 = v01, e1 = v10, o1 = v11;
                    v00 = (e0 * c0 - o0 * s0) * scale;
                    v01 = (e0 * s0 + o0 * c0) * scale;
                    v10 = (e1 * c1 - o1 * s1) * scale;
                    v11 = (e1 * s1 + o1 * c1) * scale;
                }
                unsigned ph, pl;
                {
                    const int bb = row0 / SS, s = row0 % SS;
                    const size_t pidx = (((size_t)(bb * HH + h) * SS + s) * DK + d) >> 1;
                    pack_split(ph, pl, v00, v01);
                    ((unsigned*)oh)[pidx] = ph;
                    ((unsigned*)ol)[pidx] = pl;
                }
                {
                    const int bb = row1 / SS, s = row1 % SS;
                    const size_t pidx = (((size_t)(bb * HH + h) * SS + s) * DK + d) >> 1;
                    pack_split(ph, pl, v10, v11);
                    ((unsigned*)oh)[pidx] = ph;
                    ((unsigned*)ol)[pidx] = pl;
                }
            }
        }
    }
}

// ---------------------------------------------------------------------------
// Tensor-core causal flash attention, bf16x3.
// RESHAPED: 64 q-rows / 128 threads / 4 warps per CTA, single-buffer K/V,
// 4 CTAs/SM for phase diversity (breaks softmax/mma barrier-lockstep).
// ---------------------------------------------------------------------------
__global__ __launch_bounds__(128, 4)
void attn_tc(const ushort_t* __restrict__ Qhg, const ushort_t* __restrict__ Qlg,
             const ushort_t* __restrict__ Khg, const ushort_t* __restrict__ Klg,
             const ushort_t* __restrict__ Vhg, const ushort_t* __restrict__ Vlg,
             float* __restrict__ O)
{
    extern __shared__ ushort_t smem_us[];
    ushort_t* Qh = smem_us;              // 64*PH each
    ushort_t* Ql = Qh + 64 * PH;
    ushort_t* Kh = Ql + 64 * PH;
    ushort_t* Kl = Kh + 64 * PH;
    ushort_t* Vh = Kl + 64 * PH;
    ushort_t* Vl = Vh + 64 * PH;

    const int tid  = threadIdx.x;
    const int lane = tid & 31, wid = tid >> 5;           // wid 0..3
    const int g = lane >> 2, t = lane & 3;
    const int qt = (int)gridDim.x - 1 - (int)blockIdx.x; // heavy CTAs first
    const int h = blockIdx.y, b = blockIdx.z;
    const int Q0 = qt * 64;
    const size_t hoff = (size_t)(b * HH + h) * SS * DK;

    const int grp = lane >> 3, li = lane & 7;
    const int a_r = (grp & 1) * 8 + li, a_c = (grp >> 1) * 8;   // A-frag (and V-trans)
    const int b_r = (grp >> 1) * 8 + li, b_c = (grp & 1) * 8;   // B-frag (K)

    const int lrow = tid & 63, lcq = tid >> 6;           // loader: 2 threads/row

    // ---- prologue: Q + K/V tile 0 ----
#pragma unroll
    for (int cc = 0; cc < 8; cc += 2) {
        const int c8 = (lcq + cc) * 8;
        const size_t gq = hoff + (size_t)(Q0 + lrow) * DK + c8;
        cpa16(su32(&Qh[lrow * PH + c8]), &Qhg[gq]);
        cpa16(su32(&Ql[lrow * PH + c8]), &Qlg[gq]);
        const size_t gk = hoff + (size_t)lrow * DK + c8;
        cpa16(su32(&Kh[lrow * PH + c8]), &Khg[gk]);
        cpa16(su32(&Kl[lrow * PH + c8]), &Klg[gk]);
        cpa16(su32(&Vh[lrow * PH + c8]), &Vhg[gk]);
        cpa16(su32(&Vl[lrow * PH + c8]), &Vlg[gk]);
    }
    cpa_commit();

    float o[8][4] = {};
    float m0 = -INFINITY, m1 = -INFINITY, l0 = 0.f, l1 = 0.f;  // l: per-lane partials
    const int rminl = wid * 16;
    const int rming = Q0 + rminl;

    for (int kt = 0; kt <= qt; kt++) {
        if (kt > 0) {                    // single-buffer refill
            __syncthreads();             // all readers done with previous tile
            const int C0 = kt * 64;
#pragma unroll
            for (int cc = 0; cc < 8; cc += 2) {
                const int c8 = (lcq + cc) * 8;
                const size_t gk = hoff + (size_t)(C0 + lrow) * DK + c8;
                cpa16(su32(&Kh[lrow * PH + c8]), &Khg[gk]);
                cpa16(su32(&Kl[lrow * PH + c8]), &Klg[gk]);
                cpa16(su32(&Vh[lrow * PH + c8]), &Vhg[gk]);
                cpa16(su32(&Vl[lrow * PH + c8]), &Vlg[gk]);
            }
            cpa_commit();
        }
        cpa_wait<0>();
        __syncthreads();

        // ---- S = Q K^T, bf16x3 ----
        float sc[8][4];
#pragma unroll
        for (int j = 0; j < 8; j++)
#pragma unroll
            for (int e = 0; e < 4; e++) sc[j][e] = 0.f;

#pragma unroll
        for (int ks = 0; ks < 4; ks++) {
            unsigned qh4[4], ql4[4];
            ldsm4(qh4, su32(&Qh[(rminl + a_r) * PH + 16 * ks + a_c]));
            ldsm4(ql4, su32(&Ql[(rminl + a_r) * PH + 16 * ks + a_c]));
#pragma unroll
            for (int np = 0; np < 4; np++) {
                unsigned kh4[4], kl4[4];
                ldsm4(kh4, su32(&Kh[(np * 16 + b_r) * PH + 16 * ks + b_c]));
                ldsm4(kl4, su32(&Kl[(np * 16 + b_r) * PH + 16 * ks + b_c]));
                mma_bf16(sc[2 * np],     qh4, kh4[0], kh4[1]);
                mma_bf16(sc[2 * np],     qh4, kl4[0], kl4[1]);
                mma_bf16(sc[2 * np],     ql4, kh4[0], kh4[1]);
                mma_bf16(sc[2 * np + 1], qh4, kh4[2], kh4[3]);
                mma_bf16(sc[2 * np + 1], qh4, kl4[2], kl4[3]);
                mma_bf16(sc[2 * np + 1], ql4, kh4[2], kh4[3]);
            }
        }

        // ---- causal mask: only the diagonal tile needs it ----
        if (kt == qt) {
            const int r0g = rming + g, r1g = r0g + 8;
            const int C0 = kt * 64;
#pragma unroll
            for (int j = 0; j < 8; j++) {
                const int cb = C0 + 8 * j + 2 * t;
                if (cb     > r0g) sc[j][0] = -INFINITY;
                if (cb + 1 > r0g) sc[j][1] = -INFINITY;
                if (cb     > r1g) sc[j][2] = -INFINITY;
                if (cb + 1 > r1g) sc[j][3] = -INFINITY;
            }
        }

        // ---- online softmax (log2 domain), deferred l-reduction ----
        float mx0 = -INFINITY, mx1 = -INFINITY;
#pragma unroll
        for (int j = 0; j < 8; j++) {
            mx0 = fmaxf(mx0, fmaxf(sc[j][0], sc[j][1]));
            mx1 = fmaxf(mx1, fmaxf(sc[j][2], sc[j][3]));
        }
        mx0 = fmaxf(mx0, __shfl_xor_sync(0xffffffffu, mx0, 1));
        mx0 = fmaxf(mx0, __shfl_xor_sync(0xffffffffu, mx0, 2));
        mx1 = fmaxf(mx1, __shfl_xor_sync(0xffffffffu, mx1, 1));
        mx1 = fmaxf(mx1, __shfl_xor_sync(0xffffffffu, mx1, 2));
        const float mn0 = fmaxf(m0, mx0), mn1 = fmaxf(m1, mx1);
        const float cr0 = ex2(m0 - mn0),  cr1 = ex2(m1 - mn1);
        float rs0 = 0.f, rs1 = 0.f;
#pragma unroll
        for (int j = 0; j < 8; j++) {
            sc[j][0] = ex2(sc[j][0] - mn0); rs0 += sc[j][0];
            sc[j][1] = ex2(sc[j][1] - mn0); rs0 += sc[j][1];
            sc[j][2] = ex2(sc[j][2] - mn1); rs1 += sc[j][2];
            sc[j][3] = ex2(sc[j][3] - mn1); rs1 += sc[j][3];
        }
        l0 = l0 * cr0 + rs0; l1 = l1 * cr1 + rs1;   // per-lane; reduced at epilogue
        m0 = mn0; m1 = mn1;
#pragma unroll
        for (int j = 0; j < 8; j++) {
            o[j][0] *= cr0; o[j][1] *= cr0;
            o[j][2] *= cr1; o[j][3] *= cr1;
        }

        // ---- O += P V, bf16x3 (P packed in-register) ----
#pragma unroll
        for (int cs = 0; cs < 4; cs++) {
            unsigned ph4[4], pl4[4];
            pack_split(ph4[0], pl4[0], sc[2 * cs][0],     sc[2 * cs][1]);
            pack_split(ph4[1], pl4[1], sc[2 * cs][2],     sc[2 * cs][3]);
            pack_split(ph4[2], pl4[2], sc[2 * cs + 1][0], sc[2 * cs + 1][1]);
            pack_split(ph4[3], pl4[3], sc[2 * cs + 1][2], sc[2 * cs + 1][3]);
#pragma unroll
            for (int np = 0; np < 4; np++) {
                unsigned vh4[4], vl4[4];
                ldsm4t(vh4, su32(&Vh[(cs * 16 + a_r) * PH + np * 16 + a_c]));
                ldsm4t(vl4, su32(&Vl[(cs * 16 + a_r) * PH + np * 16 + a_c]));
                mma_bf16(o[2 * np],     ph4, vh4[0], vh4[1]);
                mma_bf16(o[2 * np],     ph4, vl4[0], vl4[1]);
                mma_bf16(o[2 * np],     pl4, vh4[0], vh4[1]);
                mma_bf16(o[2 * np + 1], ph4, vh4[2], vh4[3]);
                mma_bf16(o[2 * np + 1], ph4, vl4[2], vl4[3]);
                mma_bf16(o[2 * np + 1], pl4, vh4[2], vh4[3]);
            }
        }
    }

    // ---- epilogue: finish deferred l-reduction, normalize, store ----
    l0 += __shfl_xor_sync(0xffffffffu, l0, 1);
    l0 += __shfl_xor_sync(0xffffffffu, l0, 2);
    l1 += __shfl_xor_sync(0xffffffffu, l1, 1);
    l1 += __shfl_xor_sync(0xffffffffu, l1, 2);
    const float i0 = 1.0f / l0, i1 = 1.0f / l1;
    const int r0g = Q0 + rminl + g, r1g = r0g + 8;
    float* Ob = O + (size_t)b * SS * DD + h * DK;
#pragma unroll
    for (int j = 0; j < 8; j++) {
        const int col = 8 * j + 2 * t;
        *(float2*)(Ob + (size_t)r0g * DD + col) = make_float2(o[j][0] * i0, o[j][1] * i0);
        *(float2*)(Ob + (size_t)r1g * DD + col) = make_float2(o[j][2] * i1, o[j][3] * i1);
    }
}

// ---------------------------------------------------------------------------
extern "C" void kernel_launch(void* const* d_in, const int* in_sizes, int n_in,
                              void* d_out, int out_size)
{
    const float* x  = (const float*)d_in[0];
    const int*   tp = (const int*)  d_in[1];
    const float* wq = (const float*)d_in[2];
    const float* wk = (const float*)d_in[3];
    const float* wv = (const float*)d_in[4];
    const float* wo = (const float*)d_in[5];
    float* out = (float*)d_out;

    ushort_t *qh, *ql, *kh, *kl, *vh, *vl;
    float* attn;
    cudaGetSymbolAddress((void**)&qh, g_qh);
    cudaGetSymbolAddress((void**)&ql, g_ql);
    cudaGetSymbolAddress((void**)&kh, g_kh);
    cudaGetSymbolAddress((void**)&kl, g_kl);
    cudaGetSymbolAddress((void**)&vh, g_vh);
    cudaGetSymbolAddress((void**)&vl, g_vl);
    cudaGetSymbolAddress((void**)&attn, g_attn);

    const dim3 pgrid(DD / 64, M_TOT / 128);   // (16, 32)
    const float qscale = 0.125f * 1.44269504088896340736f;  // 1/sqrt(64) * log2(e)

    proj_tc<2><<<pgrid, 256>>>(x, wq, tp, nullptr, qh, ql, qscale);
    proj_tc<2><<<pgrid, 256>>>(x, wk, tp, nullptr, kh, kl, 1.0f);
    proj_tc<1><<<pgrid, 256>>>(x, wv, tp, nullptr, vh, vl, 1.0f);

    const int asm_ = 6 * 64 * PH * 2;         // 55296 B -> 4 CTAs/SM
    cudaFuncSetAttribute(attn_tc, cudaFuncAttributeMaxDynamicSharedMemorySize, asm_);
    attn_tc<<<dim3(SS / 64, HH, BB), 128, asm_>>>(qh, ql, kh, kl, vh, vl, attn);

    proj_tc<0><<<pgrid, 256>>>(attn, wo, tp, out, nullptr, nullptr, 1.0f);
}